// round 5
// baseline (speedup 1.0000x reference)
#include <cuda_runtime.h>

#define EPS 1e-05f

// Device scratch (zero-initialized; the last block of every launch resets it
// back to zero so every graph replay starts clean).
__device__ float g_tp = 0.0f;
__device__ float g_fp = 0.0f;
__device__ float g_fn = 0.0f;
__device__ unsigned int g_count = 0u;

__device__ __forceinline__ void acc_elem(float p, int l,
                                         float& tp, float& fp, float& fn) {
    bool pp = p > 0.5f;
    bool pl = l == 1;
    tp += (pp & pl)  ? p        : 0.0f;
    fp += (pp & !pl) ? p        : 0.0f;
    fn += (!pp & pl) ? 1.0f - p : 0.0f;
}

__device__ __forceinline__ void acc4(const float4& p, const int4& l,
                                     float& tp, float& fp, float& fn) {
    acc_elem(p.x, l.x, tp, fp, fn);
    acc_elem(p.y, l.y, tp, fp, fn);
    acc_elem(p.z, l.z, tp, fp, fn);
    acc_elem(p.w, l.w, tp, fp, fn);
}

__global__ void __launch_bounds__(256)
negf1_kernel(const float4* __restrict__ probs4,
             const int4* __restrict__ lbls4,
             int n4,
             float* __restrict__ out,
             int nblocks) {
    float tp = 0.0f, fp = 0.0f, fn = 0.0f;

    const int T = gridDim.x * blockDim.x;        // total threads
    int i = blockIdx.x * blockDim.x + threadIdx.x;

    // Unrolled-by-4 main loop: issue all 8 independent 16B loads up front
    // (MLP_p1 = 8) before consuming any of them.
    for (; i + 3 * T < n4; i += 4 * T) {
        float4 p0 = probs4[i];
        float4 p1 = probs4[i + T];
        float4 p2 = probs4[i + 2 * T];
        float4 p3 = probs4[i + 3 * T];
        int4   l0 = lbls4[i];
        int4   l1 = lbls4[i + T];
        int4   l2 = lbls4[i + 2 * T];
        int4   l3 = lbls4[i + 3 * T];

        acc4(p0, l0, tp, fp, fn);
        acc4(p1, l1, tp, fp, fn);
        acc4(p2, l2, tp, fp, fn);
        acc4(p3, l3, tp, fp, fn);
    }
    // Tail (never taken when n4 % (4*T) == 0, e.g. n4 = 2^22, T = 2^18).
    for (; i < n4; i += T) {
        float4 p = probs4[i];
        int4   l = lbls4[i];
        acc4(p, l, tp, fp, fn);
    }

    // Warp reduce
    #pragma unroll
    for (int off = 16; off > 0; off >>= 1) {
        tp += __shfl_down_sync(0xFFFFFFFFu, tp, off);
        fp += __shfl_down_sync(0xFFFFFFFFu, fp, off);
        fn += __shfl_down_sync(0xFFFFFFFFu, fn, off);
    }

    __shared__ float s_tp[8], s_fp[8], s_fn[8];
    __shared__ bool  s_last;
    int lane = threadIdx.x & 31;
    int wid  = threadIdx.x >> 5;
    if (lane == 0) { s_tp[wid] = tp; s_fp[wid] = fp; s_fn[wid] = fn; }
    __syncthreads();

    if (wid == 0) {
        tp = (lane < 8) ? s_tp[lane] : 0.0f;
        fp = (lane < 8) ? s_fp[lane] : 0.0f;
        fn = (lane < 8) ? s_fn[lane] : 0.0f;
        #pragma unroll
        for (int off = 4; off > 0; off >>= 1) {
            tp += __shfl_down_sync(0xFFFFFFFFu, tp, off);
            fp += __shfl_down_sync(0xFFFFFFFFu, fp, off);
            fn += __shfl_down_sync(0xFFFFFFFFu, fn, off);
        }
        if (lane == 0) {
            atomicAdd(&g_tp, tp);
            atomicAdd(&g_fp, fp);
            atomicAdd(&g_fn, fn);
            __threadfence();
            unsigned int ticket = atomicAdd(&g_count, 1u);
            s_last = (ticket == (unsigned int)(nblocks - 1));
        }
    }
    __syncthreads();

    // Last block finalizes and resets scratch for the next graph replay.
    if (s_last && threadIdx.x == 0) {
        float TP = *(volatile float*)&g_tp;
        float FP = *(volatile float*)&g_fp;
        float FN = *(volatile float*)&g_fn;
        float precision = (TP + EPS) / (TP + FP + EPS);
        float recall    = (TP + EPS) / (TP + FN + EPS);
        float f1 = 2.0f * precision * recall / (precision + recall);
        out[0] = -f1;
        g_tp = 0.0f;
        g_fp = 0.0f;
        g_fn = 0.0f;
        g_count = 0u;
    }
}

extern "C" void kernel_launch(void* const* d_in, const int* in_sizes, int n_in,
                              void* d_out, int out_size) {
    const float* probs = (const float*)d_in[0];
    const int*   lbls  = (const int*)d_in[1];
    float* out = (float*)d_out;
    int n = in_sizes[0];
    int n4 = n >> 2;  // N = 16777216 -> n4 = 4194304 = 2^22

    int threads = 256;
    int blocks = 1024;  // 2^18 threads: n4 / T = 16 exactly -> 4 unrolled iters, no tail
    int max_blocks = (n4 + threads - 1) / threads;
    if (blocks > max_blocks) blocks = max_blocks;

    negf1_kernel<<<blocks, threads>>>((const float4*)probs, (const int4*)lbls,
                                      n4, out, blocks);
}